// round 10
// baseline (speedup 1.0000x reference)
#include <cuda_runtime.h>
#include <cuda_fp16.h>
#include <math.h>
#include <stdint.h>

// ============================================================================
// CrossAttention round 10: GEMMs reworked to 256x128 CTA tile / 64x64 warp
// tile (ldm4:MMA 1:4) with 3-stage cp.async ring + single barrier per k-tile.
// fattn unchanged from R9. B=4, Tq=Tkv=2048, DM=1024, NH=16, NKV=4, DK=64.
// ============================================================================

#define B_   4
#define TQ   2048
#define TKV  2048
#define DM   1024
#define NH   16
#define NKV  4
#define DK   64
#define KVW  (NKV * DK)      // 256
#define MTOT (B_ * TQ)       // 8192

__device__ __half g_xq [MTOT * DM];
__device__ __half g_xkv[MTOT * DM];
__device__ __half g_wq [DM * DM];
__device__ __half g_wk [KVW * DM];
__device__ __half g_wv [KVW * DM];
__device__ __half g_wo [DM * DM];
__device__ __half g_Qh [MTOT * DM];      // roped, pre-scaled 0.125*log2e
__device__ __half g_Kh [MTOT * KVW];     // roped
__device__ __half g_Vt [KVW * MTOT];     // transposed [kvh*64+d][m]
__device__ __half g_AO [MTOT * DM];

// ---------------------------------------------------------------------------
__device__ __forceinline__ unsigned pack2(float a, float b) {
    __half2 h = __floats2half2_rn(a, b);
    return *(unsigned*)&h;
}
__device__ __forceinline__ uint32_t smem_u32(const void* p) {
    uint32_t a;
    asm("{ .reg .u64 t; cvta.to.shared.u64 t, %1; cvt.u32.u64 %0, t; }"
        : "=r"(a) : "l"(p));
    return a;
}
__device__ __forceinline__ void mmaf16(float* c, const unsigned* a, const unsigned* b) {
    asm volatile(
        "mma.sync.aligned.m16n8k16.row.col.f32.f16.f16.f32 "
        "{%0,%1,%2,%3},{%4,%5,%6,%7},{%8,%9},{%0,%1,%2,%3};\n"
        : "+f"(c[0]), "+f"(c[1]), "+f"(c[2]), "+f"(c[3])
        : "r"(a[0]), "r"(a[1]), "r"(a[2]), "r"(a[3]), "r"(b[0]), "r"(b[1]));
}
__device__ __forceinline__ void ldm4(unsigned* r, uint32_t addr) {
    asm volatile("ldmatrix.sync.aligned.m8n8.x4.shared.b16 {%0,%1,%2,%3}, [%4];"
                 : "=r"(r[0]), "=r"(r[1]), "=r"(r[2]), "=r"(r[3]) : "r"(addr));
}
__device__ __forceinline__ unsigned ex2h2(unsigned x) {
    unsigned d;
    asm("ex2.approx.f16x2 %0, %1;" : "=r"(d) : "r"(x));
    return d;
}
__device__ __forceinline__ unsigned hadd2u(unsigned a, unsigned b) {
    __half2 r = __hadd2(*(__half2*)&a, *(__half2*)&b);
    return *(unsigned*)&r;
}
#define CPA16(dst, src) \
    asm volatile("cp.async.cg.shared.global [%0], [%1], 16;\n" :: "r"(dst), "l"(src))
#define CPCOMMIT() asm volatile("cp.async.commit_group;\n" ::: "memory")
#define CPWAIT(n)  asm volatile("cp.async.wait_group %0;\n" :: "n"(n) : "memory")

// ---------------------------------------------------------------------------
// Fused fp32->fp16 convert of all 6 arrays
// ---------------------------------------------------------------------------
#define C_XQ  (MTOT * DM / 4)
#define C_XKV (C_XQ  + MTOT * DM / 4)
#define C_WQ  (C_XKV + DM * DM / 4)
#define C_WK  (C_WQ  + KVW * DM / 4)
#define C_WV  (C_WK  + KVW * DM / 4)
#define C_WO  (C_WV  + DM * DM / 4)

__global__ void cvt_all(const float* __restrict__ xq, const float* __restrict__ xkv,
                        const float* __restrict__ wq, const float* __restrict__ wk,
                        const float* __restrict__ wv, const float* __restrict__ wo,
                        __half* yq, __half* ykv, __half* zq, __half* zk,
                        __half* zv, __half* zo)
{
    int i = blockIdx.x * blockDim.x + threadIdx.x;
    if (i >= C_WO) return;
    const float* s;
    __half* d;
    int off;
    if      (i < C_XQ)  { s = xq;  d = yq;  off = i; }
    else if (i < C_XKV) { s = xkv; d = ykv; off = i - C_XQ; }
    else if (i < C_WQ)  { s = wq;  d = zq;  off = i - C_XKV; }
    else if (i < C_WK)  { s = wk;  d = zk;  off = i - C_WQ; }
    else if (i < C_WV)  { s = wv;  d = zv;  off = i - C_WK; }
    else                { s = wo;  d = zo;  off = i - C_WV; }
    float4 v = ((const float4*)s)[off];
    uint2 o;
    o.x = pack2(v.x, v.y);
    o.y = pack2(v.z, v.w);
    ((uint2*)d)[off] = o;
}

// ---------------------------------------------------------------------------
// fp16 GEMM core: BM=256, BN=128, BK=64, 256 threads (8 warps, 4x2 grid,
// warp tile 64x64). 3-stage cp.async ring, ONE __syncthreads per k-tile.
// ldm4:MMA = 1:4. smem 3 x (A 36864 + W 18432) = 165888 B -> 1 CTA/SM.
// ---------------------------------------------------------------------------
#define GST 72
#define G_A_B (256 * GST * 2)       // 36864
#define G_W_B (128 * GST * 2)       // 18432
#define G_STG (G_A_B + G_W_B)       // 55296
#define GSMEM (3 * G_STG)           // 165888

struct GemmAcc { float a[4][8][4]; };

template<typename EPI>
__device__ __forceinline__ void gemm_core(
    const __half* __restrict__ A, const __half* __restrict__ W,
    int M, int N, int K, int m0b, int n0b, EPI epi)
{
    extern __shared__ __half smg[];
    const uint32_t sb = smem_u32(smg);

    const int tid  = threadIdx.x;
    const int warp = tid >> 5, lane = tid & 31;
    const int g    = lane >> 2, tig = lane & 3;
    const int wm   = warp >> 1;          // 0..3 (64-row slab)
    const int wn   = warp & 1;           // 0..1 (64-col slab)

    const int arow = (lane & 7) + 8 * ((lane >> 3) & 1);
    const int acol = 8 * (lane >> 4);
    const int brow = (lane & 7) + 8 * (lane >> 4);
    const int bcol = 8 * ((lane >> 3) & 1);

    auto stage = [&](int buf, int k0) {
        uint32_t dA = sb + buf * G_STG;
        uint32_t dW = dA + G_A_B;
#pragma unroll
        for (int t = 0; t < 8; t++) {                // A: 256x64 halves
            int c = tid + t * 256;
            int row = c >> 3, col = (c & 7) * 8;
            CPA16(dA + (row * GST + col) * 2, A + (size_t)(m0b + row) * K + k0 + col);
        }
#pragma unroll
        for (int t = 0; t < 4; t++) {                // W: 128x64 halves
            int c = tid + t * 256;
            int row = c >> 3, col = (c & 7) * 8;
            CPA16(dW + (row * GST + col) * 2, W + (size_t)(n0b + row) * K + k0 + col);
        }
    };

    GemmAcc acc;
#pragma unroll
    for (int mt = 0; mt < 4; mt++)
#pragma unroll
        for (int nt = 0; nt < 8; nt++)
#pragma unroll
            for (int r = 0; r < 4; r++) acc.a[mt][nt][r] = 0.0f;

    const int NT = K / 64;
    stage(0, 0);
    CPCOMMIT();
    stage(1, 64);
    CPCOMMIT();

    int cur = 0;
    for (int kt = 0; kt < NT; kt++) {
        if (kt + 1 < NT) { CPWAIT(1); } else { CPWAIT(0); }
        __syncthreads();
        if (kt + 2 < NT) {
            int nb = cur + 2; if (nb >= 3) nb -= 3;
            stage(nb, (kt + 2) * 64);
            CPCOMMIT();
        }

        const uint32_t aB = sb + cur * G_STG + ((wm * 64 + arow) * GST + acol) * 2;
        const uint32_t bB = sb + cur * G_STG + G_A_B + ((wn * 64 + brow) * GST + bcol) * 2;

#pragma unroll
        for (int kk = 0; kk < 64; kk += 16) {
            unsigned a[4][4];
#pragma unroll
            for (int mt = 0; mt < 4; mt++)
                ldm4(a[mt], aB + (mt * 16 * GST + kk) * 2);
#pragma unroll
            for (int ntp = 0; ntp < 4; ntp++) {
                unsigned bb[4];
                ldm4(bb, bB + (kk + ntp * 16 * GST) * 2);
#pragma unroll
                for (int mt = 0; mt < 4; mt++) {
                    mmaf16(acc.a[mt][2 * ntp],     a[mt], bb);
                    mmaf16(acc.a[mt][2 * ntp + 1], a[mt], bb + 2);
                }
            }
        }
        if (++cur >= 3) cur = 0;
    }
    epi(acc, wm, wn, g, tig);
}

// ---- RoPE + fp16 epilogue (cols j and j+32 of a head in nt / nt+4) ----
__device__ __forceinline__ void rope_epi(
    const GemmAcc& acc, __half* Ch, int M, int N, int m0b, int n0b,
    int wm, int wn, int g, int tig, float qs)
{
#pragma unroll
    for (int nt = 0; nt < 4; nt++) {
        int j0 = nt * 8 + tig * 2;
        float i0 = exp2f(-0.4152410118609203f * (float)j0);
        float i1 = exp2f(-0.4152410118609203f * (float)(j0 + 1));
#pragma unroll
        for (int mt = 0; mt < 4; mt++) {
#pragma unroll
            for (int rr = 0; rr < 2; rr++) {
                int row = m0b + wm * 64 + mt * 16 + g + 8 * rr;
                float tpos = (float)(row & (TQ - 1));
                float s0, c0, s1, c1;
                sincosf(tpos * i0, &s0, &c0);
                sincosf(tpos * i1, &s1, &c1);
                float x1a = acc.a[mt][nt][2 * rr];
                float x1b = acc.a[mt][nt][2 * rr + 1];
                float x2a = acc.a[mt][nt + 4][2 * rr];
                float x2b = acc.a[mt][nt + 4][2 * rr + 1];
                unsigned lo = pack2((x1a * c0 - x2a * s0) * qs,
                                    (x1b * c1 - x2b * s1) * qs);
                unsigned hi = pack2((x1a * s0 + x2a * c0) * qs,
                                    (x1b * s1 + x2b * c1) * qs);
                int col = n0b + wn * 64 + nt * 8 + tig * 2;
                *(unsigned*)(Ch + (size_t)row * N + col)      = lo;
                *(unsigned*)(Ch + (size_t)row * N + col + 32) = hi;
            }
        }
    }
}

__global__ __launch_bounds__(256, 1) void gemm_q(
    const __half* __restrict__ A, const __half* __restrict__ W,
    __half* __restrict__ C)
{
    const int m0b = blockIdx.y * 256, n0b = blockIdx.x * 128;
    gemm_core(A, W, MTOT, DM, DM, m0b, n0b,
        [&](const GemmAcc& acc, int wm, int wn, int g, int tig) {
            rope_epi(acc, C, MTOT, DM, m0b, n0b, wm, wn, g, tig,
                     0.18033688011112042f);   // 0.125 * log2(e)
        });
}

__global__ __launch_bounds__(256, 1) void gemm_kv(
    const __half* __restrict__ A, const __half* __restrict__ Wk,
    const __half* __restrict__ Wv, __half* __restrict__ Ck,
    __half* __restrict__ Cv)
{
    const int m0b = blockIdx.y * 256, n0b = blockIdx.x * 128;
    const int z = blockIdx.z;
    const __half* W = z ? Wv : Wk;
    gemm_core(A, W, MTOT, KVW, DM, m0b, n0b,
        [&](const GemmAcc& acc, int wm, int wn, int g, int tig) {
            if (z == 0) {
                rope_epi(acc, Ck, MTOT, KVW, m0b, n0b, wm, wn, g, tig, 1.0f);
            } else {
#pragma unroll
                for (int mt = 0; mt < 4; mt++) {
                    int row = m0b + wm * 64 + mt * 16 + g;
#pragma unroll
                    for (int nt = 0; nt < 8; nt++) {
                        int col = n0b + wn * 64 + nt * 8 + tig * 2;
                        Cv[(size_t)col       * MTOT + row]     = __float2half(acc.a[mt][nt][0]);
                        Cv[(size_t)(col + 1) * MTOT + row]     = __float2half(acc.a[mt][nt][1]);
                        Cv[(size_t)col       * MTOT + row + 8] = __float2half(acc.a[mt][nt][2]);
                        Cv[(size_t)(col + 1) * MTOT + row + 8] = __float2half(acc.a[mt][nt][3]);
                    }
                }
            }
        });
}

__global__ __launch_bounds__(256, 1) void gemm_o(
    const __half* __restrict__ A, const __half* __restrict__ W,
    float* __restrict__ C)
{
    const int m0b = blockIdx.y * 256, n0b = blockIdx.x * 128;
    gemm_core(A, W, MTOT, DM, DM, m0b, n0b,
        [&](const GemmAcc& acc, int wm, int wn, int g, int tig) {
#pragma unroll
            for (int mt = 0; mt < 4; mt++) {
                int row = m0b + wm * 64 + mt * 16 + g;
#pragma unroll
                for (int nt = 0; nt < 8; nt++) {
                    int col = n0b + wn * 64 + nt * 8 + tig * 2;
                    *(float2*)(C + (size_t)row * DM + col) =
                        make_float2(acc.a[mt][nt][0], acc.a[mt][nt][1]);
                    *(float2*)(C + (size_t)(row + 8) * DM + col) =
                        make_float2(acc.a[mt][nt][2], acc.a[mt][nt][3]);
                }
            }
        });
}

// ---------------------------------------------------------------------------
// Flash attention (R9): 128 threads (4 warps x 32 q rows), 2 CTAs/SM,
// 3-stage cp.async KV ring, ONE __syncthreads per kv tile,
// Q frags in registers, ldmatrix K/V, log2-domain no-max softmax.
// ---------------------------------------------------------------------------
#define AST 72
#define QROWS 128
#define KVSTG 3
#define STGB  (2 * 64 * AST * 2)
#define ATTN_SMEM ((QROWS * AST * 2) + KVSTG * STGB)   // 73728 B

__global__ __launch_bounds__(128, 2) void fattn(
    const __half* __restrict__ Qh, const __half* __restrict__ Kh,
    const __half* __restrict__ Vt, __half* __restrict__ O)
{
    extern __shared__ __half sh[];
    __half* Qs = sh;
    const uint32_t sb   = smem_u32(sh);
    const uint32_t stb  = sb + QROWS * AST * 2;

    const int b  = blockIdx.z;
    const int h  = blockIdx.y;
    const int q0 = blockIdx.x * QROWS;
    const int kvh = h >> 2;

    const int tid  = threadIdx.x;
    const int warp = tid >> 5, lane = tid & 31;
    const int g    = lane >> 2, tig = lane & 3;

    const int arow = (lane & 7) + 8 * ((lane >> 3) & 1);
    const int acol = 8 * (lane >> 4);
    const int brow = (lane & 7) + 8 * (lane >> 4);
    const int bcol = 8 * ((lane >> 3) & 1);

    const __half* Qg = Qh + (size_t)(b * TQ + q0) * DM + h * DK;
    const __half* Kg = Kh + (size_t)(b * TKV) * KVW + kvh * DK;
    const __half* Vg = Vt + (size_t)(kvh * DK) * MTOT + b * TKV;

    auto stage_kv = [&](int buf, int kv0) {
        uint32_t dK = stb + buf * STGB;
        uint32_t dV = dK + 64 * AST * 2;
#pragma unroll
        for (int i = 0; i < 4; i++) {
            int flat = tid + i * 128;
            int row = flat >> 3;
            int col = (flat & 7) * 8;
            CPA16(dK + (row * AST + col) * 2, Kg + (size_t)(kv0 + row) * KVW + col);
            CPA16(dV + (row * AST + col) * 2, Vg + (size_t)row * MTOT + kv0 + col);
        }
    };

#pragma unroll
    for (int i = 0; i < 8; i++) {
        int flat = tid + i * 128;
        int row = flat >> 3;
        int col = (flat & 7) * 8;
        *(int4*)&Qs[row * AST + col] = *(const int4*)(Qg + (size_t)row * DM + col);
    }
    stage_kv(0, 0);
    CPCOMMIT();
    stage_kv(1, 64);
    CPCOMMIT();
    __syncthreads();

    unsigned qa[2][4][4];
#pragma unroll
    for (int mt = 0; mt < 2; mt++) {
        uint32_t qB = sb + ((warp * 32 + mt * 16 + arow) * AST + acol) * 2;
#pragma unroll
        for (int kk = 0; kk < 4; kk++) ldm4(qa[mt][kk], qB + kk * 16 * 2);
    }

    float lsum[2][2] = {{0.0f, 0.0f}, {0.0f, 0.0f}};
    float oc[2][8][4];
#pragma unroll
    for (int mt = 0; mt < 2; mt++)
#pragma unroll
        for (int nt = 0; nt < 8; nt++)
#pragma unroll
            for (int r = 0; r < 4; r++) oc[mt][nt][r] = 0.0f;

    const int NT = TKV / 64;   // 32
    int cur = 0;
    for (int kt = 0; kt < NT; kt++) {
        if (kt + 1 < NT) { CPWAIT(1); } else { CPWAIT(0); }
        __syncthreads();
        if (kt + 2 < NT) {
            int nb = cur + 2; if (nb >= KVSTG) nb -= KVSTG;
            stage_kv(nb, (kt + 2) * 64);
            CPCOMMIT();
        }

        const uint32_t kB = stb + cur * STGB + (brow * AST + bcol) * 2;
        const uint32_t vB = kB + 64 * AST * 2;

        float sc[2][8][4];
#pragma unroll
        for (int mt = 0; mt < 2; mt++)
#pragma unroll
            for (int nt = 0; nt < 8; nt++)
#pragma unroll
                for (int r = 0; r < 4; r++) sc[mt][nt][r] = 0.0f;

#pragma unroll
        for (int kk = 0; kk < 4; kk++) {
#pragma unroll
            for (int ntp = 0; ntp < 4; ntp++) {
                unsigned bb[4];
                ldm4(bb, kB + kk * 16 * 2 + ntp * 16 * AST * 2);
#pragma unroll
                for (int mt = 0; mt < 2; mt++) {
                    mmaf16(sc[mt][2 * ntp],     qa[mt][kk], bb);
                    mmaf16(sc[mt][2 * ntp + 1], qa[mt][kk], bb + 2);
                }
            }
        }

        unsigned pf[2][8][2];
#pragma unroll
        for (int mt = 0; mt < 2; mt++) {
#pragma unroll
            for (int nt = 0; nt < 8; nt++) {
                pf[mt][nt][0] = ex2h2(pack2(sc[mt][nt][0], sc[mt][nt][1]));
                pf[mt][nt][1] = ex2h2(pack2(sc[mt][nt][2], sc[mt][nt][3]));
            }
#pragma unroll
            for (int r = 0; r < 2; r++) {
                unsigned u = hadd2u(hadd2u(hadd2u(pf[mt][0][r], pf[mt][1][r]),
                                           hadd2u(pf[mt][2][r], pf[mt][3][r])),
                                    hadd2u(hadd2u(pf[mt][4][r], pf[mt][5][r]),
                                           hadd2u(pf[mt][6][r], pf[mt][7][r])));
                float2 f = __half22float2(*(__half2*)&u);
                lsum[mt][r] += f.x + f.y;
            }
        }

#pragma unroll
        for (int kk = 0; kk < 4; kk++) {
#pragma unroll
            for (int ntp = 0; ntp < 4; ntp++) {
                unsigned bb[4];
                ldm4(bb, vB + kk * 16 * 2 + ntp * 16 * AST * 2);
#pragma unroll
                for (int mt = 0; mt < 2; mt++) {
                    unsigned a[4] = {pf[mt][2 * kk][0], pf[mt][2 * kk][1],
                                     pf[mt][2 * kk + 1][0], pf[mt][2 * kk + 1][1]};
                    mmaf16(oc[mt][2 * ntp],     a, bb);
                    mmaf16(oc[mt][2 * ntp + 1], a, bb + 2);
                }
            }
        }

        if (++cur >= KVSTG) cur = 0;
    }

#pragma unroll
    for (int mt = 0; mt < 2; mt++) {
#pragma unroll
        for (int r = 0; r < 2; r++) {
            lsum[mt][r] += __shfl_xor_sync(0xffffffffu, lsum[mt][r], 1);
            lsum[mt][r] += __shfl_xor_sync(0xffffffffu, lsum[mt][r], 2);
        }
        float inv0 = 1.0f / lsum[mt][0];
        float inv1 = 1.0f / lsum[mt][1];
        __half* Og = O + (size_t)(b * TQ + q0 + warp * 32 + mt * 16) * DM + h * DK;
#pragma unroll
        for (int nt = 0; nt < 8; nt++) {
            *(unsigned*)(Og + (size_t)g * DM + nt * 8 + tig * 2) =
                pack2(oc[mt][nt][0] * inv0, oc[mt][nt][1] * inv0);
            *(unsigned*)(Og + (size_t)(g + 8) * DM + nt * 8 + tig * 2) =
                pack2(oc[mt][nt][2] * inv1, oc[mt][nt][3] * inv1);
        }
    }
}

// ---------------------------------------------------------------------------
// Launch
// ---------------------------------------------------------------------------
extern "C" void kernel_launch(void* const* d_in, const int* in_sizes, int n_in,
                              void* d_out, int out_size)
{
    const float* query = (const float*)d_in[0];
    const float* kv    = (const float*)d_in[1];
    const float* Wq = (const float*)d_in[4];
    const float* Wk = (const float*)d_in[5];
    const float* Wv = (const float*)d_in[6];
    const float* Wo = (const float*)d_in[7];
    float* out = (float*)d_out;

    __half *xq, *xkv, *wq, *wk, *wv, *wo, *Qhb, *Khb, *Vtb, *AOb;
    cudaGetSymbolAddress((void**)&xq,  g_xq);
    cudaGetSymbolAddress((void**)&xkv, g_xkv);
    cudaGetSymbolAddress((void**)&wq,  g_wq);
    cudaGetSymbolAddress((void**)&wk,  g_wk);
    cudaGetSymbolAddress((void**)&wv,  g_wv);
    cudaGetSymbolAddress((void**)&wo,  g_wo);
    cudaGetSymbolAddress((void**)&Qhb, g_Qh);
    cudaGetSymbolAddress((void**)&Khb, g_Kh);
    cudaGetSymbolAddress((void**)&Vtb, g_Vt);
    cudaGetSymbolAddress((void**)&AOb, g_AO);

    cvt_all<<<(C_WO + 255) / 256, 256>>>(query, kv, Wq, Wk, Wv, Wo,
                                         xq, xkv, wq, wk, wv, wo);

    cudaFuncSetAttribute(gemm_q,  cudaFuncAttributeMaxDynamicSharedMemorySize, GSMEM);
    cudaFuncSetAttribute(gemm_kv, cudaFuncAttributeMaxDynamicSharedMemorySize, GSMEM);
    cudaFuncSetAttribute(gemm_o,  cudaFuncAttributeMaxDynamicSharedMemorySize, GSMEM);

    gemm_q <<<dim3(DM / 128,  MTOT / 256),    256, GSMEM>>>(xq,  wq, Qhb);
    gemm_kv<<<dim3(KVW / 128, MTOT / 256, 2), 256, GSMEM>>>(xkv, wk, wv, Khb, Vtb);

    cudaFuncSetAttribute(fattn, cudaFuncAttributeMaxDynamicSharedMemorySize,
                         ATTN_SMEM);
    fattn<<<dim3(TQ / QROWS, NH, B_), 128, ATTN_SMEM>>>(Qhb, Khb, Vtb, AOb);

    gemm_o<<<dim3(DM / 128, MTOT / 256), 256, GSMEM>>>(AOb, wo, out);
}

// round 11
// speedup vs baseline: 1.1618x; 1.1618x over previous
#include <cuda_runtime.h>
#include <cuda_fp16.h>
#include <math.h>
#include <stdint.h>

// ============================================================================
// CrossAttention round 11: R7 GEMM config restored + Q/K/V projections fused
// into ONE launch + fattn exp/PV half-tile interleave (MUFU-tensor overlap).
// B=4, Tq=Tkv=2048, DM=1024, NH=16, NKV=4 (GQA), DK=64, RoPE base 1e4.
// ============================================================================

#define B_   4
#define TQ   2048
#define TKV  2048
#define DM   1024
#define NH   16
#define NKV  4
#define DK   64
#define KVW  (NKV * DK)      // 256
#define MTOT (B_ * TQ)       // 8192

__device__ __half g_xq [MTOT * DM];
__device__ __half g_xkv[MTOT * DM];
__device__ __half g_wq [DM * DM];
__device__ __half g_wk [KVW * DM];
__device__ __half g_wv [KVW * DM];
__device__ __half g_wo [DM * DM];
__device__ __half g_Qh [MTOT * DM];      // roped, pre-scaled 0.125*log2e
__device__ __half g_Kh [MTOT * KVW];     // roped
__device__ __half g_Vt [KVW * MTOT];     // transposed [kvh*64+d][m]
__device__ __half g_AO [MTOT * DM];

// ---------------------------------------------------------------------------
__device__ __forceinline__ unsigned pack2(float a, float b) {
    __half2 h = __floats2half2_rn(a, b);
    return *(unsigned*)&h;
}
__device__ __forceinline__ uint32_t smem_u32(const void* p) {
    uint32_t a;
    asm("{ .reg .u64 t; cvta.to.shared.u64 t, %1; cvt.u32.u64 %0, t; }"
        : "=r"(a) : "l"(p));
    return a;
}
__device__ __forceinline__ void mmaf16(float* c, const unsigned* a, const unsigned* b) {
    asm volatile(
        "mma.sync.aligned.m16n8k16.row.col.f32.f16.f16.f32 "
        "{%0,%1,%2,%3},{%4,%5,%6,%7},{%8,%9},{%0,%1,%2,%3};\n"
        : "+f"(c[0]), "+f"(c[1]), "+f"(c[2]), "+f"(c[3])
        : "r"(a[0]), "r"(a[1]), "r"(a[2]), "r"(a[3]), "r"(b[0]), "r"(b[1]));
}
__device__ __forceinline__ void ldm4(unsigned* r, uint32_t addr) {
    asm volatile("ldmatrix.sync.aligned.m8n8.x4.shared.b16 {%0,%1,%2,%3}, [%4];"
                 : "=r"(r[0]), "=r"(r[1]), "=r"(r[2]), "=r"(r[3]) : "r"(addr));
}
__device__ __forceinline__ unsigned ex2h2(unsigned x) {
    unsigned d;
    asm("ex2.approx.f16x2 %0, %1;" : "=r"(d) : "r"(x));
    return d;
}
__device__ __forceinline__ unsigned hadd2u(unsigned a, unsigned b) {
    __half2 r = __hadd2(*(__half2*)&a, *(__half2*)&b);
    return *(unsigned*)&r;
}
#define CPA16(dst, src) \
    asm volatile("cp.async.cg.shared.global [%0], [%1], 16;\n" :: "r"(dst), "l"(src))
#define CPCOMMIT() asm volatile("cp.async.commit_group;\n" ::: "memory")
#define CPWAIT(n)  asm volatile("cp.async.wait_group %0;\n" :: "n"(n) : "memory")

// ---------------------------------------------------------------------------
// Fused fp32->fp16 convert of all 6 arrays
// ---------------------------------------------------------------------------
#define C_XQ  (MTOT * DM / 4)
#define C_XKV (C_XQ  + MTOT * DM / 4)
#define C_WQ  (C_XKV + DM * DM / 4)
#define C_WK  (C_WQ  + KVW * DM / 4)
#define C_WV  (C_WK  + KVW * DM / 4)
#define C_WO  (C_WV  + DM * DM / 4)

__global__ void cvt_all(const float* __restrict__ xq, const float* __restrict__ xkv,
                        const float* __restrict__ wq, const float* __restrict__ wk,
                        const float* __restrict__ wv, const float* __restrict__ wo,
                        __half* yq, __half* ykv, __half* zq, __half* zk,
                        __half* zv, __half* zo)
{
    int i = blockIdx.x * blockDim.x + threadIdx.x;
    if (i >= C_WO) return;
    const float* s;
    __half* d;
    int off;
    if      (i < C_XQ)  { s = xq;  d = yq;  off = i; }
    else if (i < C_XKV) { s = xkv; d = ykv; off = i - C_XQ; }
    else if (i < C_WQ)  { s = wq;  d = zq;  off = i - C_XKV; }
    else if (i < C_WK)  { s = wk;  d = zk;  off = i - C_WQ; }
    else if (i < C_WV)  { s = wv;  d = zv;  off = i - C_WK; }
    else                { s = wo;  d = zo;  off = i - C_WV; }
    float4 v = ((const float4*)s)[off];
    uint2 o;
    o.x = pack2(v.x, v.y);
    o.y = pack2(v.z, v.w);
    ((uint2*)d)[off] = o;
}

// ---------------------------------------------------------------------------
// fp16 GEMM core (R7, best measured): BM=BN=128, BK=64, 256 thr,
// cp.async 2-stage, ldmatrix fragment loads. smem 73728 B, 2 CTAs/SM.
// ---------------------------------------------------------------------------
#define GST 72
#define GBUF (128 * GST)
#define GSMEM (4 * GBUF * 2)

struct GemmAcc { float a[2][8][4]; };

template<typename EPI>
__device__ __forceinline__ void gemm_core(
    const __half* __restrict__ A, const __half* __restrict__ W,
    int M, int N, int K, int m0b, int n0b, EPI epi)
{
    extern __shared__ __half smg[];
    const uint32_t sb = smem_u32(smg);

    const int tid  = threadIdx.x;
    const int warp = tid >> 5, lane = tid & 31;
    const int g    = lane >> 2, tig = lane & 3;
    const int wm   = warp >> 1;
    const int wn   = warp & 1;

    const int arow = (lane & 7) + 8 * ((lane >> 3) & 1);
    const int acol = 8 * (lane >> 4);
    const int brow = (lane & 7) + 8 * (lane >> 4);
    const int bcol = 8 * ((lane >> 3) & 1);

    auto stage = [&](int b, int k0) {
        uint32_t dA = sb + b * (2 * GBUF * 2);
        uint32_t dW = dA + GBUF * 2;
#pragma unroll
        for (int t = 0; t < 4; t++) {
            int idx = tid + t * 256;
            int row = idx >> 3;
            int col = (idx & 7) * 8;
            CPA16(dA + (row * GST + col) * 2, A + (size_t)(m0b + row) * K + k0 + col);
            CPA16(dW + (row * GST + col) * 2, W + (size_t)(n0b + row) * K + k0 + col);
        }
    };

    GemmAcc acc;
#pragma unroll
    for (int mt = 0; mt < 2; mt++)
#pragma unroll
        for (int nt = 0; nt < 8; nt++)
#pragma unroll
            for (int r = 0; r < 4; r++) acc.a[mt][nt][r] = 0.0f;

    const int NT = K / 64;
    stage(0, 0);
    CPCOMMIT();

    for (int kt = 0; kt < NT; kt++) {
        const int cur = kt & 1;
        if (kt + 1 < NT) {
            stage(cur ^ 1, (kt + 1) * 64);
            CPCOMMIT();
            CPWAIT(1);
        } else {
            CPWAIT(0);
        }
        __syncthreads();

        const uint32_t aB = sb + cur * (2 * GBUF * 2)
                          + ((wm * 32 + arow) * GST + acol) * 2;
        const uint32_t bB = sb + cur * (2 * GBUF * 2) + GBUF * 2
                          + ((wn * 64 + brow) * GST + bcol) * 2;

#pragma unroll
        for (int kk = 0; kk < 64; kk += 16) {
            unsigned a[2][4];
            ldm4(a[0], aB + kk * 2);
            ldm4(a[1], aB + kk * 2 + 16 * GST * 2);
#pragma unroll
            for (int ntp = 0; ntp < 4; ntp++) {
                unsigned bb[4];
                ldm4(bb, bB + kk * 2 + ntp * 16 * GST * 2);
#pragma unroll
                for (int mt = 0; mt < 2; mt++) {
                    mmaf16(acc.a[mt][2 * ntp],     a[mt], bb);
                    mmaf16(acc.a[mt][2 * ntp + 1], a[mt], bb + 2);
                }
            }
        }
        __syncthreads();
    }
    epi(acc, wm, wn, g, tig);
}

// ---- RoPE + fp16 epilogue ----
__device__ __forceinline__ void rope_epi(
    const GemmAcc& acc, __half* Ch, int M, int N, int m0b, int n0b,
    int wm, int wn, int g, int tig, float qs)
{
#pragma unroll
    for (int nt = 0; nt < 4; nt++) {
        int j0 = nt * 8 + tig * 2;
        float i0 = exp2f(-0.4152410118609203f * (float)j0);
        float i1 = exp2f(-0.4152410118609203f * (float)(j0 + 1));
#pragma unroll
        for (int mt = 0; mt < 2; mt++) {
#pragma unroll
            for (int rr = 0; rr < 2; rr++) {
                int row = m0b + wm * 32 + mt * 16 + g + 8 * rr;
                float tpos = (float)(row & (TQ - 1));
                float s0, c0, s1, c1;
                sincosf(tpos * i0, &s0, &c0);
                sincosf(tpos * i1, &s1, &c1);
                float x1a = acc.a[mt][nt][2 * rr];
                float x1b = acc.a[mt][nt][2 * rr + 1];
                float x2a = acc.a[mt][nt + 4][2 * rr];
                float x2b = acc.a[mt][nt + 4][2 * rr + 1];
                unsigned lo = pack2((x1a * c0 - x2a * s0) * qs,
                                    (x1b * c1 - x2b * s1) * qs);
                unsigned hi = pack2((x1a * s0 + x2a * c0) * qs,
                                    (x1b * s1 + x2b * c1) * qs);
                int col = n0b + wn * 64 + nt * 8 + tig * 2;
                *(unsigned*)(Ch + (size_t)row * N + col)      = lo;
                *(unsigned*)(Ch + (size_t)row * N + col + 32) = hi;
            }
        }
    }
}

// ---- fused Q+K+V projection: one launch, 768 CTAs ----
// id < 512      : Q proj (RoPE, scale 0.125*log2e), grid 8n x 64m
// 512 <= id<640 : K proj (RoPE),                    grid 2n x 64m
// 640 <= id<768 : V proj (fp16 transposed),         grid 2n x 64m
__global__ __launch_bounds__(256, 2) void gemm_qkv(
    const __half* __restrict__ xq, const __half* __restrict__ xkv,
    const __half* __restrict__ wq, const __half* __restrict__ wk,
    const __half* __restrict__ wv,
    __half* __restrict__ Qh, __half* __restrict__ Kh, __half* __restrict__ Vt)
{
    const int id = blockIdx.x;
    if (id < 512) {
        const int m0b = (id >> 3) * 128, n0b = (id & 7) * 128;
        gemm_core(xq, wq, MTOT, DM, DM, m0b, n0b,
            [&](const GemmAcc& acc, int wm, int wn, int g, int tig) {
                rope_epi(acc, Qh, MTOT, DM, m0b, n0b, wm, wn, g, tig,
                         0.18033688011112042f);   // 0.125 * log2(e)
            });
    } else if (id < 640) {
        const int id2 = id - 512;
        const int m0b = (id2 >> 1) * 128, n0b = (id2 & 1) * 128;
        gemm_core(xkv, wk, MTOT, KVW, DM, m0b, n0b,
            [&](const GemmAcc& acc, int wm, int wn, int g, int tig) {
                rope_epi(acc, Kh, MTOT, KVW, m0b, n0b, wm, wn, g, tig, 1.0f);
            });
    } else {
        const int id2 = id - 640;
        const int m0b = (id2 >> 1) * 128, n0b = (id2 & 1) * 128;
        gemm_core(xkv, wv, MTOT, KVW, DM, m0b, n0b,
            [&](const GemmAcc& acc, int wm, int wn, int g, int tig) {
#pragma unroll
                for (int mt = 0; mt < 2; mt++) {
                    int row = m0b + wm * 32 + mt * 16 + g;
#pragma unroll
                    for (int nt = 0; nt < 8; nt++) {
                        int col = n0b + wn * 64 + nt * 8 + tig * 2;
                        Vt[(size_t)col       * MTOT + row]     = __float2half(acc.a[mt][nt][0]);
                        Vt[(size_t)(col + 1) * MTOT + row]     = __float2half(acc.a[mt][nt][1]);
                        Vt[(size_t)col       * MTOT + row + 8] = __float2half(acc.a[mt][nt][2]);
                        Vt[(size_t)(col + 1) * MTOT + row + 8] = __float2half(acc.a[mt][nt][3]);
                    }
                }
            });
    }
}

// ---- output projection (R7 config) ----
__global__ __launch_bounds__(256, 2) void gemm_o(
    const __half* __restrict__ A, const __half* __restrict__ W,
    float* __restrict__ C)
{
    const int m0b = blockIdx.y * 128, n0b = blockIdx.x * 128;
    gemm_core(A, W, MTOT, DM, DM, m0b, n0b,
        [&](const GemmAcc& acc, int wm, int wn, int g, int tig) {
#pragma unroll
            for (int mt = 0; mt < 2; mt++) {
                int row = m0b + wm * 32 + mt * 16 + g;
#pragma unroll
                for (int nt = 0; nt < 8; nt++) {
                    int col = n0b + wn * 64 + nt * 8 + tig * 2;
                    *(float2*)(C + (size_t)row * DM + col) =
                        make_float2(acc.a[mt][nt][0], acc.a[mt][nt][1]);
                    *(float2*)(C + (size_t)(row + 8) * DM + col) =
                        make_float2(acc.a[mt][nt][2], acc.a[mt][nt][3]);
                }
            }
        });
}

// ---------------------------------------------------------------------------
// Flash attention (R9 base): 128 threads (4 warps x 32 q rows), 2 CTAs/SM,
// 3-stage cp.async KV ring, one __syncthreads per kv tile. NEW: exp and PV
// interleaved at half-tile granularity so MUFU overlaps tensor within a warp:
//   S(all) -> exp(kv 0..31) -> PV(kv 0..31) -> exp(kv 32..63) -> PV(kv 32..63)
// ---------------------------------------------------------------------------
#define AST 72
#define QROWS 128
#define KVSTG 3
#define STGB  (2 * 64 * AST * 2)
#define ATTN_SMEM ((QROWS * AST * 2) + KVSTG * STGB)   // 73728 B

__global__ __launch_bounds__(128, 2) void fattn(
    const __half* __restrict__ Qh, const __half* __restrict__ Kh,
    const __half* __restrict__ Vt, __half* __restrict__ O)
{
    extern __shared__ __half sh[];
    __half* Qs = sh;
    const uint32_t sb   = smem_u32(sh);
    const uint32_t stb  = sb + QROWS * AST * 2;

    const int b  = blockIdx.z;
    const int h  = blockIdx.y;
    const int q0 = blockIdx.x * QROWS;
    const int kvh = h >> 2;

    const int tid  = threadIdx.x;
    const int warp = tid >> 5, lane = tid & 31;
    const int g    = lane >> 2, tig = lane & 3;

    const int arow = (lane & 7) + 8 * ((lane >> 3) & 1);
    const int acol = 8 * (lane >> 4);
    const int brow = (lane & 7) + 8 * (lane >> 4);
    const int bcol = 8 * ((lane >> 3) & 1);

    const __half* Qg = Qh + (size_t)(b * TQ + q0) * DM + h * DK;
    const __half* Kg = Kh + (size_t)(b * TKV) * KVW + kvh * DK;
    const __half* Vg = Vt + (size_t)(kvh * DK) * MTOT + b * TKV;

    auto stage_kv = [&](int buf, int kv0) {
        uint32_t dK = stb + buf * STGB;
        uint32_t dV = dK + 64 * AST * 2;
#pragma unroll
        for (int i = 0; i < 4; i++) {
            int flat = tid + i * 128;
            int row = flat >> 3;
            int col = (flat & 7) * 8;
            CPA16(dK + (row * AST + col) * 2, Kg + (size_t)(kv0 + row) * KVW + col);
            CPA16(dV + (row * AST + col) * 2, Vg + (size_t)row * MTOT + kv0 + col);
        }
    };

#pragma unroll
    for (int i = 0; i < 8; i++) {
        int flat = tid + i * 128;
        int row = flat >> 3;
        int col = (flat & 7) * 8;
        *(int4*)&Qs[row * AST + col] = *(const int4*)(Qg + (size_t)row * DM + col);
    }
    stage_kv(0, 0);
    CPCOMMIT();
    stage_kv(1, 64);
    CPCOMMIT();
    __syncthreads();

    unsigned qa[2][4][4];
#pragma unroll
    for (int mt = 0; mt < 2; mt++) {
        uint32_t qB = sb + ((warp * 32 + mt * 16 + arow) * AST + acol) * 2;
#pragma unroll
        for (int kk = 0; kk < 4; kk++) ldm4(qa[mt][kk], qB + kk * 16 * 2);
    }

    float lsum[2][2] = {{0.0f, 0.0f}, {0.0f, 0.0f}};
    float oc[2][8][4];
#pragma unroll
    for (int mt = 0; mt < 2; mt++)
#pragma unroll
        for (int nt = 0; nt < 8; nt++)
#pragma unroll
            for (int r = 0; r < 4; r++) oc[mt][nt][r] = 0.0f;

    const int NT = TKV / 64;   // 32
    int cur = 0;
    for (int kt = 0; kt < NT; kt++) {
        if (kt + 1 < NT) { CPWAIT(1); } else { CPWAIT(0); }
        __syncthreads();
        if (kt + 2 < NT) {
            int nb = cur + 2; if (nb >= KVSTG) nb -= KVSTG;
            stage_kv(nb, (kt + 2) * 64);
            CPCOMMIT();
        }

        const uint32_t kB = stb + cur * STGB + (brow * AST + bcol) * 2;
        const uint32_t vB = kB + 64 * AST * 2;

        // ---- S = Q K^T (all 64 kv cols) ----
        float sc[2][8][4];
#pragma unroll
        for (int mt = 0; mt < 2; mt++)
#pragma unroll
            for (int nt = 0; nt < 8; nt++)
#pragma unroll
                for (int r = 0; r < 4; r++) sc[mt][nt][r] = 0.0f;

#pragma unroll
        for (int kk = 0; kk < 4; kk++) {
#pragma unroll
            for (int ntp = 0; ntp < 4; ntp++) {
                unsigned bb[4];
                ldm4(bb, kB + kk * 16 * 2 + ntp * 16 * AST * 2);
#pragma unroll
                for (int mt = 0; mt < 2; mt++) {
                    mmaf16(sc[mt][2 * ntp],     qa[mt][kk], bb);
                    mmaf16(sc[mt][2 * ntp + 1], qa[mt][kk], bb + 2);
                }
            }
        }

        unsigned pf[2][8][2];

        // ---- half A: exp for kv cols 0..31 (nt 0..3) + partial lsum ----
#pragma unroll
        for (int mt = 0; mt < 2; mt++) {
#pragma unroll
            for (int nt = 0; nt < 4; nt++) {
                pf[mt][nt][0] = ex2h2(pack2(sc[mt][nt][0], sc[mt][nt][1]));
                pf[mt][nt][1] = ex2h2(pack2(sc[mt][nt][2], sc[mt][nt][3]));
            }
#pragma unroll
            for (int r = 0; r < 2; r++) {
                unsigned u = hadd2u(hadd2u(pf[mt][0][r], pf[mt][1][r]),
                                    hadd2u(pf[mt][2][r], pf[mt][3][r]));
                float2 f = __half22float2(*(__half2*)&u);
                lsum[mt][r] += f.x + f.y;
            }
        }

        // ---- PV for kv rows 0..31 (kk 0,1) — overlaps with exp half B ----
#pragma unroll
        for (int kk = 0; kk < 2; kk++) {
#pragma unroll
            for (int ntp = 0; ntp < 4; ntp++) {
                unsigned bb[4];
                ldm4(bb, vB + kk * 16 * 2 + ntp * 16 * AST * 2);
#pragma unroll
                for (int mt = 0; mt < 2; mt++) {
                    unsigned a[4] = {pf[mt][2 * kk][0], pf[mt][2 * kk][1],
                                     pf[mt][2 * kk + 1][0], pf[mt][2 * kk + 1][1]};
                    mmaf16(oc[mt][2 * ntp],     a, bb);
                    mmaf16(oc[mt][2 * ntp + 1], a, bb + 2);
                }
            }
        }

        // ---- half B: exp for kv cols 32..63 (nt 4..7) + partial lsum ----
#pragma unroll
        for (int mt = 0; mt < 2; mt++) {
#pragma unroll
            for (int nt = 4; nt < 8; nt++) {
                pf[mt][nt][0] = ex2h2(pack2(sc[mt][nt][0], sc[mt][nt][1]));
                pf[mt][nt][1] = ex2h2(pack2(sc[mt][nt][2], sc[mt][nt][3]));
            }
#pragma unroll
            for (int r = 0; r < 2; r++) {
                unsigned u = hadd2u(hadd2u(pf[mt][4][r], pf[mt][5][r]),
                                    hadd2u(pf[mt][6][r], pf[mt][7][r]));
                float2 f = __half22float2(*(__half2*)&u);
                lsum[mt][r] += f.x + f.y;
            }
        }

        // ---- PV for kv rows 32..63 (kk 2,3) ----
#pragma unroll
        for (int kk = 2; kk < 4; kk++) {
#pragma unroll
            for (int ntp = 0; ntp < 4; ntp++) {
                unsigned bb[4];
                ldm4(bb, vB + kk * 16 * 2 + ntp * 16 * AST * 2);
#pragma unroll
                for (int mt = 0; mt < 2; mt++) {
                    unsigned a[4] = {pf[mt][2 * kk][0], pf[mt][2 * kk][1],
                                     pf[mt][2 * kk + 1][0], pf[mt][2 * kk + 1][1]};
                    mmaf16(oc[mt][2 * ntp],     a, bb);
                    mmaf16(oc[mt][2 * ntp + 1], a, bb + 2);
                }
            }
        }

        if (++cur >= KVSTG) cur = 0;
    }

#pragma unroll
    for (int mt = 0; mt < 2; mt++) {
#pragma unroll
        for (int r = 0; r < 2; r++) {
            lsum[mt][r] += __shfl_xor_sync(0xffffffffu, lsum[mt][r], 1);
            lsum[mt][r] += __shfl_xor_sync(0xffffffffu, lsum[mt][r], 2);
        }
        float inv0 = 1.0f / lsum[mt][0];
        float inv1 = 1.0f / lsum[mt][1];
        __half* Og = O + (size_t)(b * TQ + q0 + warp * 32 + mt * 16) * DM + h * DK;
#pragma unroll
        for (int nt = 0; nt < 8; nt++) {
            *(unsigned*)(Og + (size_t)g * DM + nt * 8 + tig * 2) =
                pack2(oc[mt][nt][0] * inv0, oc[mt][nt][1] * inv0);
            *(unsigned*)(Og + (size_t)(g + 8) * DM + nt * 8 + tig * 2) =
                pack2(oc[mt][nt][2] * inv1, oc[mt][nt][3] * inv1);
        }
    }
}

// ---------------------------------------------------------------------------
// Launch
// ---------------------------------------------------------------------------
extern "C" void kernel_launch(void* const* d_in, const int* in_sizes, int n_in,
                              void* d_out, int out_size)
{
    const float* query = (const float*)d_in[0];
    const float* kv    = (const float*)d_in[1];
    const float* Wq = (const float*)d_in[4];
    const float* Wk = (const float*)d_in[5];
    const float* Wv = (const float*)d_in[6];
    const float* Wo = (const float*)d_in[7];
    float* out = (float*)d_out;

    __half *xq, *xkv, *wq, *wk, *wv, *wo, *Qhb, *Khb, *Vtb, *AOb;
    cudaGetSymbolAddress((void**)&xq,  g_xq);
    cudaGetSymbolAddress((void**)&xkv, g_xkv);
    cudaGetSymbolAddress((void**)&wq,  g_wq);
    cudaGetSymbolAddress((void**)&wk,  g_wk);
    cudaGetSymbolAddress((void**)&wv,  g_wv);
    cudaGetSymbolAddress((void**)&wo,  g_wo);
    cudaGetSymbolAddress((void**)&Qhb, g_Qh);
    cudaGetSymbolAddress((void**)&Khb, g_Kh);
    cudaGetSymbolAddress((void**)&Vtb, g_Vt);
    cudaGetSymbolAddress((void**)&AOb, g_AO);

    cvt_all<<<(C_WO + 255) / 256, 256>>>(query, kv, Wq, Wk, Wv, Wo,
                                         xq, xkv, wq, wk, wv, wo);

    cudaFuncSetAttribute(gemm_qkv, cudaFuncAttributeMaxDynamicSharedMemorySize, GSMEM);
    cudaFuncSetAttribute(gemm_o,   cudaFuncAttributeMaxDynamicSharedMemorySize, GSMEM);

    gemm_qkv<<<768, 256, GSMEM>>>(xq, xkv, wq, wk, wv, Qhb, Khb, Vtb);

    cudaFuncSetAttribute(fattn, cudaFuncAttributeMaxDynamicSharedMemorySize,
                         ATTN_SMEM);
    fattn<<<dim3(TQ / QROWS, NH, B_), 128, ATTN_SMEM>>>(Qhb, Khb, Vtb, AOb);

    gemm_o<<<dim3(DM / 128, MTOT / 128), 256, GSMEM>>>(AOb, wo, out);
}